// round 6
// baseline (speedup 1.0000x reference)
#include <cuda_runtime.h>

#define SS 9
#define FF 32

constexpr int N_MAX = 16384;
constexpr int E_MAX = 524288;

__device__ int g_count[N_MAX];
__device__ int g_offset[N_MAX + 1];
__device__ int g_cursor[N_MAX];
__device__ int g_edges[E_MAX];

typedef unsigned long long u64t;

__device__ __forceinline__ u64t pk2(float lo, float hi) {
    u64t r;
    asm("mov.b64 %0, {%1,%2};" : "=l"(r) : "f"(lo), "f"(hi));
    return r;
}
__device__ __forceinline__ void upk2(u64t v, float& lo, float& hi) {
    asm("mov.b64 {%0,%1}, %2;" : "=f"(lo), "=f"(hi) : "l"(v));
}
__device__ __forceinline__ u64t fma2(u64t a, u64t b, u64t c) {
    u64t d;
    asm("fma.rn.f32x2 %0, %1, %2, %3;" : "=l"(d) : "l"(a), "l"(b), "l"(c));
    return d;
}
__device__ __forceinline__ u64t mul2(u64t a, u64t b) {
    u64t d;
    asm("mul.rn.f32x2 %0, %1, %2;" : "=l"(d) : "l"(a), "l"(b));
    return d;
}

__device__ __forceinline__ float envelope_f(float d) {
    float u = fminf(fmaxf(d, 0.0f), 1.0f);
    float u2 = u * u;
    float u4 = u2 * u2;
    float u5 = u4 * u;
    return 1.0f + u5 * (-21.0f + u * (35.0f - 15.0f * u));
}

__global__ void zero_counts(int n) {
    int i = blockIdx.x * blockDim.x + threadIdx.x;
    if (i < n) g_count[i] = 0;
}

__global__ void hist_kernel(const int* __restrict__ ei, int e_cnt) {
    int i = blockIdx.x * blockDim.x + threadIdx.x;
    if (i < e_cnt) atomicAdd(&g_count[ei[e_cnt + i]], 1);
}

__global__ void scan_kernel(int n) {
    __shared__ int part[1024];
    int tid = threadIdx.x;
    int ch = (n + 1023) >> 10;
    int base = tid * ch;
    int s = 0;
    for (int i = 0; i < ch; i++) {
        int idx = base + i;
        if (idx < n) s += g_count[idx];
    }
    part[tid] = s;
    __syncthreads();
    for (int off = 1; off < 1024; off <<= 1) {
        int v = (tid >= off) ? part[tid - off] : 0;
        __syncthreads();
        part[tid] += v;
        __syncthreads();
    }
    int run = (tid > 0) ? part[tid - 1] : 0;
    for (int i = 0; i < ch; i++) {
        int idx = base + i;
        if (idx < n) {
            g_offset[idx] = run;
            g_cursor[idx] = run;
            run += g_count[idx];
        }
    }
    if (tid == 1023) g_offset[n] = part[1023];
}

__global__ void scatter_kernel(const int* __restrict__ ei, int e_cnt) {
    int i = blockIdx.x * blockDim.x + threadIdx.x;
    if (i < e_cnt) {
        int d = ei[e_cnt + i];
        int pos = atomicAdd(&g_cursor[d], 1);
        g_edges[pos] = i;
    }
}

// ---------------- aggregate: edge-paired f32x2 ----------------
// One warp per destination node; lane = feature f (F == 32).
// Edges processed in PAIRS; f32x2 halves = (edge_i, edge_{i+1}).
// smem A holds packed (env_y0_i*A_i[p,q], env_y0_j*A_j[p,q]) at u64 index p*10+q.
// msg_a folded into the matvec accumulator via rl = wwl/wml; epilogue scales by wml.

struct PairData {
    float x0[SS], x1[SS];
    float ya0[SS], ya1[SS];
    float d0, d1;
};

__device__ __forceinline__ void load_pair(
    PairData& P, const float* __restrict__ x, const int* __restrict__ ei,
    const float2* __restrict__ ea2, int start, int len, int i, int lane)
{
    int c0 = (i     < len) ? i     : len - 1;
    int c1 = (i + 1 < len) ? i + 1 : len - 1;
    bool pad0 = (i     >= len);
    bool pad1 = (i + 1 >= len);
    int e0 = g_edges[start + c0];
    int e1 = g_edges[start + c1];
    int s0 = ei[e0], s1 = ei[e1];
    const float* xb0 = x + (size_t)s0 * (SS * FF) + lane;
    const float* xb1 = x + (size_t)s1 * (SS * FF) + lane;
#pragma unroll
    for (int q = 0; q < SS; q++) { P.x0[q] = xb0[q * FF]; P.x1[q] = xb1[q * FF]; }
    const float2* yb0 = ea2 + (size_t)e0 * SS;
    const float2* yb1 = ea2 + (size_t)e1 * SS;
#pragma unroll
    for (int s = 0; s < SS; s++) {
        float2 v0 = yb0[s];
        float2 v1 = yb1[s];
        P.ya0[s] = pad0 ? 0.0f : v0.x;
        P.ya1[s] = pad1 ? 0.0f : v1.x;
        if (s == 0) { P.d0 = v0.y; P.d1 = v1.y; }
    }
}

__device__ __forceinline__ void compute_pair(
    const PairData& P, u64t* __restrict__ awb,
    const float (&cgr)[3][SS], const int (&saddr)[3], const bool (&valid)[3],
    const u64t (&rl2)[3], u64t (&acc2)[SS])
{
    const int lv[SS] = {0, 1, 1, 1, 2, 2, 2, 2, 2};

    float ey00 = envelope_f(P.ya0[0]);
    float ey01 = envelope_f(P.ya1[0]);
    float ed0  = envelope_f(P.d0);
    float ed1  = envelope_f(P.d1);

    // A build: both edges scalar, env_y0 folded, packed store
#pragma unroll
    for (int j = 0; j < 3; j++) {
        float a0 = cgr[j][0] * P.ya0[0];
        float a1 = cgr[j][0] * P.ya1[0];
#pragma unroll
        for (int r = 1; r < SS; r++) {
            a0 = fmaf(cgr[j][r], P.ya0[r], a0);
            a1 = fmaf(cgr[j][r], P.ya1[r], a1);
        }
        if (valid[j]) awb[saddr[j]] = pk2(a0 * ey00, a1 * ey01);
    }
    __syncwarp();

    u64t envd2 = pk2(ed0, ed1);
    u64t xq2[SS], c2[SS];
#pragma unroll
    for (int q = 0; q < SS; q++) {
        xq2[q] = pk2(P.x0[q], P.x1[q]);
        u64t t = mul2(pk2(P.ya0[q], P.ya1[q]), envd2);
        c2[q] = mul2(t, rl2[lv[q]]);
    }

    // packed matvec + diag, accumulate in place
#pragma unroll
    for (int p = 0; p < SS; p++) {
        const u64t* row = awb + p * 10;
        const ulonglong2 r01 = *(const ulonglong2*)(row);
        const ulonglong2 r23 = *(const ulonglong2*)(row + 2);
        const ulonglong2 r45 = *(const ulonglong2*)(row + 4);
        const ulonglong2 r67 = *(const ulonglong2*)(row + 6);
        const u64t       r8  = row[8];
        u64t m = acc2[p];
        m = fma2(r01.x, xq2[0], m);
        m = fma2(r01.y, xq2[1], m);
        m = fma2(r23.x, xq2[2], m);
        m = fma2(r23.y, xq2[3], m);
        m = fma2(r45.x, xq2[4], m);
        m = fma2(r45.y, xq2[5], m);
        m = fma2(r67.x, xq2[6], m);
        m = fma2(r67.y, xq2[7], m);
        m = fma2(r8,    xq2[8], m);
        m = fma2(c2[p], xq2[p], m);
        acc2[p] = m;
    }
}

__global__ __launch_bounds__(128) void aggregate_kernel(
    const float* __restrict__ x,
    const int*   __restrict__ ei,
    const float* __restrict__ ea,
    const float* __restrict__ cgg,
    const float* __restrict__ Wsca,
    const float* __restrict__ Wsph,
    const float* __restrict__ Wmix,
    float* __restrict__ out,
    int n, int e_cnt)
{
    __shared__ __align__(16) u64t s_aw[4][2][96];  // [warp][buf][p*10+q]

    int tid  = threadIdx.x;
    int w    = tid >> 5;
    int lane = tid & 31;
    int node = blockIdx.x * 4 + w;
    if (node >= n) return;

    const int lv[SS] = {0, 1, 1, 1, 2, 2, 2, 2, 2};

    float wwl[3], wml[3];
    u64t rl2[3];
#pragma unroll
    for (int l = 0; l < 3; l++) {
        wwl[l] = Wsca[l * 32 + lane] * Wsph[l * 32 + lane];
        wml[l] = Wmix[l * 32 + lane];
        float rl = wwl[l] / wml[l];
        rl2[l] = pk2(rl, rl);
    }

    // Loop-invariant cg rows: lane owns k in {lane, lane+32, lane+64}
    float cgr[3][SS];
    int   saddr[3];
    bool  valid[3];
#pragma unroll
    for (int j = 0; j < 3; j++) {
        int k = lane + j * 32;
        valid[j] = (k < 81);
        int kk = valid[j] ? k : 0;
        int p = kk / 9, q = kk - p * 9;
        saddr[j] = p * 10 + q;
#pragma unroll
        for (int r = 0; r < SS; r++) cgr[j][r] = cgg[kk * 9 + r];
    }

    u64t acc2[SS];
#pragma unroll
    for (int p = 0; p < SS; p++) acc2[p] = 0ull;

    int start = g_offset[node];
    int end   = g_offset[node + 1];
    int len   = end - start;

    const float2* __restrict__ ea2 = (const float2*)ea;

    if (len > 0) {
        PairData A, B;
        load_pair(A, x, ei, ea2, start, len, 0, lane);
        int i = 0;
        while (true) {
            load_pair(B, x, ei, ea2, start, len, i + 2, lane);
            compute_pair(A, s_aw[w][0], cgr, saddr, valid, rl2, acc2);
            i += 2;
            if (i >= len) break;
            load_pair(A, x, ei, ea2, start, len, i + 2, lane);
            compute_pair(B, s_aw[w][1], cgr, saddr, valid, rl2, acc2);
            i += 2;
            if (i >= len) break;
        }
    }

    // epilogue: out = x + wml * (lo + hi)
    const float* xn = x   + (size_t)node * (SS * FF) + lane;
    float*       on = out + (size_t)node * (SS * FF) + lane;
#pragma unroll
    for (int p = 0; p < SS; p++) {
        float lo, hi;
        upk2(acc2[p], lo, hi);
        on[p * FF] = xn[p * FF] + wml[lv[p]] * (lo + hi);
    }
}

extern "C" void kernel_launch(void* const* d_in, const int* in_sizes, int n_in,
                              void* d_out, int out_size)
{
    const float* x    = (const float*)d_in[0];
    const int*   ei   = (const int*)  d_in[1];
    const float* ea   = (const float*)d_in[2];
    const float* wsca = (const float*)d_in[3];
    const float* wsph = (const float*)d_in[4];
    const float* wmix = (const float*)d_in[5];
    const float* cgg  = (const float*)d_in[6];
    float* out = (float*)d_out;

    int n = in_sizes[0] / (SS * FF);
    int e = in_sizes[1] / 2;

    zero_counts<<<(n + 255) / 256, 256>>>(n);
    hist_kernel<<<(e + 255) / 256, 256>>>(ei, e);
    scan_kernel<<<1, 1024>>>(n);
    scatter_kernel<<<(e + 255) / 256, 256>>>(ei, e);
    aggregate_kernel<<<(n + 3) / 4, 128>>>(x, ei, ea, cgg, wsca, wsph, wmix, out, n, e);
}

// round 8
// speedup vs baseline: 1.2013x; 1.2013x over previous
#include <cuda_runtime.h>

#define SS 9
#define FF 32

constexpr int N_MAX = 16384;
constexpr int E_MAX = 524288;

__device__ int g_count[N_MAX];
__device__ int g_offset[N_MAX + 1];
__device__ int g_cursor[N_MAX];
__device__ int g_edges[E_MAX];
// Per-edge precomputed coefficients: [0..8]=env(Y0)*Y[s], [9..17]=env(d)*Y[s], [18..19]=pad
__device__ float g_ecoef[(size_t)E_MAX * 20];

typedef unsigned long long u64t;

__device__ __forceinline__ u64t pk2(float lo, float hi) {
    u64t r;
    asm("mov.b64 %0, {%1,%2};" : "=l"(r) : "f"(lo), "f"(hi));
    return r;
}
__device__ __forceinline__ void upk2(u64t v, float& lo, float& hi) {
    asm("mov.b64 {%0,%1}, %2;" : "=f"(lo), "=f"(hi) : "l"(v));
}
__device__ __forceinline__ u64t fma2(u64t a, u64t b, u64t c) {
    u64t d;
    asm("fma.rn.f32x2 %0, %1, %2, %3;" : "=l"(d) : "l"(a), "l"(b), "l"(c));
    return d;
}
__device__ __forceinline__ u64t mul2(u64t a, u64t b) {
    u64t d;
    asm("mul.rn.f32x2 %0, %1, %2;" : "=l"(d) : "l"(a), "l"(b));
    return d;
}

__device__ __forceinline__ float envelope_f(float d) {
    float u = fminf(fmaxf(d, 0.0f), 1.0f);
    float u2 = u * u;
    float u4 = u2 * u2;
    float u5 = u4 * u;
    return 1.0f + u5 * (-21.0f + u * (35.0f - 15.0f * u));
}

__global__ void zero_counts(int n) {
    int i = blockIdx.x * blockDim.x + threadIdx.x;
    if (i < n) g_count[i] = 0;
}

__global__ void hist_kernel(const int* __restrict__ ei, int e_cnt) {
    int i = blockIdx.x * blockDim.x + threadIdx.x;
    if (i < e_cnt) atomicAdd(&g_count[ei[e_cnt + i]], 1);
}

__global__ void scan_kernel(int n) {
    __shared__ int part[1024];
    int tid = threadIdx.x;
    int ch = (n + 1023) >> 10;
    int base = tid * ch;
    int s = 0;
    for (int i = 0; i < ch; i++) {
        int idx = base + i;
        if (idx < n) s += g_count[idx];
    }
    part[tid] = s;
    __syncthreads();
    for (int off = 1; off < 1024; off <<= 1) {
        int v = (tid >= off) ? part[tid - off] : 0;
        __syncthreads();
        part[tid] += v;
        __syncthreads();
    }
    int run = (tid > 0) ? part[tid - 1] : 0;
    for (int i = 0; i < ch; i++) {
        int idx = base + i;
        if (idx < n) {
            g_offset[idx] = run;
            g_cursor[idx] = run;
            run += g_count[idx];
        }
    }
    if (tid == 1023) g_offset[n] = part[1023];
}

__global__ void scatter_kernel(const int* __restrict__ ei, int e_cnt) {
    int i = blockIdx.x * blockDim.x + threadIdx.x;
    if (i < e_cnt) {
        int d = ei[e_cnt + i];
        int pos = atomicAdd(&g_cursor[d], 1);
        g_edges[pos] = i;
    }
}

// Precompute per-edge coefficient block (bandwidth-bound, ~80MB traffic)
__global__ void edge_coef_kernel(const float* __restrict__ ea, int e_cnt) {
    int e = blockIdx.x * blockDim.x + threadIdx.x;
    if (e >= e_cnt) return;
    const float2* yb = (const float2*)ea + (size_t)e * SS;
    float Y[SS], d = 0.0f;
#pragma unroll
    for (int s = 0; s < SS; s++) {
        float2 v = yb[s];
        Y[s] = v.x;
        if (s == 0) d = v.y;
    }
    float ey0 = envelope_f(Y[0]);
    float ed  = envelope_f(d);
    float o[20];
#pragma unroll
    for (int s = 0; s < SS; s++) {
        o[s]     = ey0 * Y[s];
        o[9 + s] = ed  * Y[s];
    }
    o[18] = 0.0f; o[19] = 0.0f;
    float4* dst = (float4*)(g_ecoef + (size_t)e * 20);
#pragma unroll
    for (int v = 0; v < 5; v++)
        dst[v] = make_float4(o[4 * v], o[4 * v + 1], o[4 * v + 2], o[4 * v + 3]);
}

// One warp per destination node; lane = feature f (F == 32).
// cg rows in registers; A (with env_y0 pre-folded via Ysc) stored to smem
// PAIR-INTERLEAVED so the mixed matvec runs on fma.rn.f32x2.
// msg_a diag folded via rl = wwl/wml; epilogue scales by wml.
__global__ __launch_bounds__(128) void aggregate_kernel(
    const float* __restrict__ x,
    const int*   __restrict__ ei,
    const float* __restrict__ cgg,
    const float* __restrict__ Wsca,
    const float* __restrict__ Wsph,
    const float* __restrict__ Wmix,
    float* __restrict__ out,
    int n, int e_cnt)
{
    __shared__ __align__(16) float s_aw[4][2][112];  // [warp][buf][pair-interleaved A]

    int tid  = threadIdx.x;
    int w    = tid >> 5;
    int lane = tid & 31;
    int node = blockIdx.x * 4 + w;
    if (node >= n) return;

    const int lv[SS] = {0, 1, 1, 1, 2, 2, 2, 2, 2};

    float wml[3], rl[3];
#pragma unroll
    for (int l = 0; l < 3; l++) {
        float ww = Wsca[l * 32 + lane] * Wsph[l * 32 + lane];
        wml[l] = Wmix[l * 32 + lane];
        rl[l]  = ww / wml[l];
    }
    // packed rl for adjacent-p pairs: (lv[2pr], lv[2pr+1])
    u64t rlp2[4];
    rlp2[0] = pk2(rl[0], rl[1]);
    rlp2[1] = pk2(rl[1], rl[1]);
    rlp2[2] = pk2(rl[2], rl[2]);
    rlp2[3] = rlp2[2];
    float rl8 = rl[2];

    // Loop-invariant cg rows: lane owns k in {lane, lane+32, lane+64}
    float cgr[3][SS];
    int   saddr[3];
    bool  valid[3];
#pragma unroll
    for (int j = 0; j < 3; j++) {
        int k = lane + j * 32;
        valid[j] = (k < 81);
        int kk = valid[j] ? k : 0;
        int p = kk / 9, q = kk - p * 9;
        saddr[j] = (p < 8) ? ((p >> 1) * 24 + q * 2 + (p & 1)) : (96 + q);
#pragma unroll
        for (int r = 0; r < SS; r++) cgr[j][r] = cgg[kk * 9 + r];
    }

    u64t acc2[4];
#pragma unroll
    for (int i = 0; i < 4; i++) acc2[i] = 0ull;
    float acc8 = 0.0f;

    int start = g_offset[node];
    int end   = g_offset[node + 1];

    float xq[SS], xqn[SS];
    float cf[18], cfn[18];  // [0..8]=Ysc, [9..17]=c

    if (start < end) {
        int e0 = g_edges[start];
        int s0 = ei[e0];
        const float* xb = x + (size_t)s0 * (SS * FF) + lane;
#pragma unroll
        for (int q = 0; q < SS; q++) xq[q] = xb[q * FF];
        const float4* cb = (const float4*)(g_ecoef + (size_t)e0 * 20);
#pragma unroll
        for (int v = 0; v < 4; v++) {
            float4 t = cb[v];
            cf[4 * v] = t.x; cf[4 * v + 1] = t.y; cf[4 * v + 2] = t.z; cf[4 * v + 3] = t.w;
        }
        { float4 t = cb[4]; cf[16] = t.x; cf[17] = t.y; }
    }

    int buf = 0;
    for (int i = start; i < end; ++i) {
        int inx = (i + 1 < end) ? (i + 1) : i;
        int en  = g_edges[inx];
        int sn  = ei[en];
        const float* xbn  = x + (size_t)sn * (SS * FF) + lane;
        const float4* cbn = (const float4*)(g_ecoef + (size_t)en * 20);

        // ---- A build (scalar FFMA from Ysc; env_y0 already folded) ----
        float* awb = s_aw[w][buf];
#pragma unroll
        for (int j = 0; j < 3; j++) {
            float a = cgr[j][0] * cf[0];
#pragma unroll
            for (int r = 1; r < SS; r++) a = fmaf(cgr[j][r], cf[r], a);
            if (valid[j]) awb[saddr[j]] = a;
        }
        __syncwarp();

        // ---- prefetch next edge (overlaps compute below) ----
#pragma unroll
        for (int q = 0; q < SS; q++) xqn[q] = xbn[q * FF];
#pragma unroll
        for (int v = 0; v < 4; v++) {
            float4 t = cbn[v];
            cfn[4 * v] = t.x; cfn[4 * v + 1] = t.y; cfn[4 * v + 2] = t.z; cfn[4 * v + 3] = t.w;
        }
        { float4 t = cbn[4]; cfn[16] = t.x; cfn[17] = t.y; }

        // ---- packed operands ----
        u64t xq2[SS], xp2[4], c2[4];
#pragma unroll
        for (int q = 0; q < SS; q++) xq2[q] = pk2(xq[q], xq[q]);
#pragma unroll
        for (int i2 = 0; i2 < 4; i2++) {
            xp2[i2] = pk2(xq[2 * i2], xq[2 * i2 + 1]);
            c2[i2]  = mul2(pk2(cf[9 + 2 * i2], cf[9 + 2 * i2 + 1]), rlp2[i2]);
        }
        float c8 = cf[17] * rl8;

        // ---- packed mixed matvec over 4 p-pairs (+ folded diag) ----
#pragma unroll
        for (int pr = 0; pr < 4; pr++) {
            const float* rb = awb + pr * 24;
            const ulonglong2 u0 = *(const ulonglong2*)(rb);
            const ulonglong2 u1 = *(const ulonglong2*)(rb + 4);
            const ulonglong2 u2 = *(const ulonglong2*)(rb + 8);
            const ulonglong2 u3 = *(const ulonglong2*)(rb + 12);
            const u64t       u4 = *(const u64t*)(rb + 16);
            u64t m = acc2[pr];
            m = fma2(u0.x, xq2[0], m);
            m = fma2(u0.y, xq2[1], m);
            m = fma2(u1.x, xq2[2], m);
            m = fma2(u1.y, xq2[3], m);
            m = fma2(u2.x, xq2[4], m);
            m = fma2(u2.y, xq2[5], m);
            m = fma2(u3.x, xq2[6], m);
            m = fma2(u3.y, xq2[7], m);
            m = fma2(u4,   xq2[8], m);
            m = fma2(c2[pr], xp2[pr], m);
            acc2[pr] = m;
        }
        // ---- scalar p = 8 row ----
        {
            const float* a8 = awb + 96;
            float m = fmaf(a8[0], xq[0], acc8);
#pragma unroll
            for (int q = 1; q < SS; q++) m = fmaf(a8[q], xq[q], m);
            acc8 = fmaf(c8, xq[8], m);
        }

        // ---- rotate prefetch ----
#pragma unroll
        for (int q = 0; q < SS; q++) xq[q] = xqn[q];
#pragma unroll
        for (int v = 0; v < 18; v++) cf[v] = cfn[v];
        buf ^= 1;
    }

    // epilogue: out = x + wml * acc
    const float* xn = x   + (size_t)node * (SS * FF) + lane;
    float*       on = out + (size_t)node * (SS * FF) + lane;
#pragma unroll
    for (int pr = 0; pr < 4; pr++) {
        float lo, hi;
        upk2(acc2[pr], lo, hi);
        on[(2 * pr)     * FF] = xn[(2 * pr)     * FF] + wml[lv[2 * pr]]     * lo;
        on[(2 * pr + 1) * FF] = xn[(2 * pr + 1) * FF] + wml[lv[2 * pr + 1]] * hi;
    }
    on[8 * FF] = xn[8 * FF] + wml[2] * acc8;
}

extern "C" void kernel_launch(void* const* d_in, const int* in_sizes, int n_in,
                              void* d_out, int out_size)
{
    const float* x    = (const float*)d_in[0];
    const int*   ei   = (const int*)  d_in[1];
    const float* ea   = (const float*)d_in[2];
    const float* wsca = (const float*)d_in[3];
    const float* wsph = (const float*)d_in[4];
    const float* wmix = (const float*)d_in[5];
    const float* cgg  = (const float*)d_in[6];
    float* out = (float*)d_out;

    int n = in_sizes[0] / (SS * FF);
    int e = in_sizes[1] / 2;

    zero_counts<<<(n + 255) / 256, 256>>>(n);
    hist_kernel<<<(e + 255) / 256, 256>>>(ei, e);
    edge_coef_kernel<<<(e + 255) / 256, 256>>>(ea, e);
    scan_kernel<<<1, 1024>>>(n);
    scatter_kernel<<<(e + 255) / 256, 256>>>(ei, e);
    aggregate_kernel<<<(n + 3) / 4, 128>>>(x, ei, cgg, wsca, wsph, wmix, out, n, e);
}